// round 3
// baseline (speedup 1.0000x reference)
#include <cuda_runtime.h>
#include <cstddef>

// Problem constants (fixed by setup_inputs)
#define RB   12
#define LB   32
#define MB   16
#define HHB  32
#define HFB  64
#define EB   132
#define BTOT 64
#define NGROUP 12
#define NBLOCKS (NGROUP*RB)
#define NTHREADS 192   // 6 warps
#define MAXWB 6

__device__ unsigned g_flag[NGROUP][MAXWB][RB];

struct __align__(16) SmemLayout {
    // weights, row-per-output, padded strides (conflict-free LDS.128)
    float mw2[11*16*36];   // [slot][m][k] stride 36
    float aw2[11*32*20];   // [slot][l][m] stride 20
    float mb [11*16];
    float gsw2[32*36];     // [o][i]
    float gcw2[32*36];
    float gsb[32];
    float lw2[64*68];      // [o][i0..63]
    float lbS[64];
    float ow2[32*68];      // [l][hf]
    float obS[32];
    float wih2[96*36];     // [j][i]
    float whh2[96*36];
    float bihS[96];
    float bhhS[96];
    // activations (per batch)
    float zs   [MAXWB][RB][LB];
    float meanS[MAXWB][11][16];
    float part [MAXWB][MAXWB][LB];   // [warp][batch][l]
    float incS [MAXWB][LB];
    float gparts[MAXWB][LB];
    float lwz  [MAXWB][HFB];
    float ghS  [MAXWB][96];
    float giS  [MAXWB][96];
    float hbuf [MAXWB][HFB];
    float gateS[MAXWB][LB];
    float hg   [MAXWB][HHB];
    int   elist[12];
    int   slist[12];
};

__device__ __forceinline__ float fsig(float x) { return 1.0f / (1.0f + __expf(-x)); }

__device__ __forceinline__ void st_release(unsigned* p, unsigned v) {
    asm volatile("st.release.gpu.u32 [%0], %1;" :: "l"(p), "r"(v) : "memory");
}
__device__ __forceinline__ unsigned ld_acquire(unsigned* p) {
    unsigned v;
    asm volatile("ld.acquire.gpu.u32 %0, [%1];" : "=r"(v) : "l"(p) : "memory");
    return v;
}

__global__ void nv_init_kernel() {
    unsigned* p = &g_flag[0][0][0];
    const int n = NGROUP*MAXWB*RB;
    for (int i = threadIdx.x; i < n; i += blockDim.x) p[i] = 0u;
}

__global__ void __launch_bounds__(NTHREADS, 1) nv_main_kernel(
    const float* __restrict__ z0,  const float* __restrict__ h0,
    const float* __restrict__ mean_w, const float* __restrict__ mean_b,
    const float* __restrict__ add_w,
    const float* __restrict__ gsw, const float* __restrict__ gsb_g,
    const float* __restrict__ gcw,
    const float* __restrict__ lw,  const float* __restrict__ lb_g,
    const float* __restrict__ ow,  const float* __restrict__ ob_g,
    const float* __restrict__ wih, const float* __restrict__ whh,
    const float* __restrict__ bih_g, const float* __restrict__ bhh_g,
    const int* __restrict__ src_idx, const int* __restrict__ tgt_idx,
    int T,
    float* __restrict__ zt, float* __restrict__ hf, float* __restrict__ ms)
{
    extern __shared__ char smraw[];
    SmemLayout& sm = *reinterpret_cast<SmemLayout*>(smraw);
    const int tid = threadIdx.x;
    const int g = blockIdx.x / RB;
    const int r = blockIdx.x % RB;

    const int nb = (g < 4) ? 6 : 5;
    const int b0 = g * 5 + (g < 4 ? g : 4);

    // ---- incoming-edge list for region r ----
    for (int e = tid; e < EB; e += NTHREADS) {
        if (tgt_idx[e] == r) {
            int s = src_idx[e];
            int slot = (s < r) ? s : s - 1;
            sm.elist[slot] = e;
            sm.slist[slot] = s;
        }
    }
    __syncthreads();

    // ---- cache weights to smem ----
    for (int idx = tid; idx < 11*MB*LB; idx += NTHREADS) {
        int slot = idx / (MB*LB); int rem = idx % (MB*LB);
        int m = rem / LB, k = rem % LB;
        int e = sm.elist[slot];
        sm.mw2[(slot*16 + m)*36 + k] = mean_w[((size_t)e*MB + m)*LB + k];
    }
    for (int idx = tid; idx < 11*LB*MB; idx += NTHREADS) {
        int slot = idx / (LB*MB); int rem = idx % (LB*MB);
        int l = rem / MB, m = rem % MB;
        int e = sm.elist[slot];
        sm.aw2[(slot*32 + l)*20 + m] = add_w[((size_t)e*LB + l)*MB + m];
    }
    for (int idx = tid; idx < 11*MB; idx += NTHREADS) {
        int slot = idx / MB, m = idx % MB;
        sm.mb[idx] = mean_b[sm.elist[slot]*MB + m];
    }
    for (int idx = tid; idx < LB*LB; idx += NTHREADS) {
        int o = idx / LB, i = idx % LB;
        sm.gsw2[o*36 + i] = gsw[((size_t)r*LB + o)*LB + i];
        sm.gcw2[o*36 + i] = gcw[((size_t)r*LB + o)*LB + i];
    }
    if (tid < LB) sm.gsb[tid] = gsb_g[r*LB + tid];
    for (int idx = tid; idx < HFB*2*LB; idx += NTHREADS) {
        int o = idx / (2*LB), i = idx % (2*LB);
        sm.lw2[o*68 + i] = lw[((size_t)r*HFB + o)*(2*LB) + i];
    }
    if (tid < HFB) sm.lbS[tid] = lb_g[r*HFB + tid];
    for (int idx = tid; idx < LB*HFB; idx += NTHREADS) {
        int l = idx / HFB, i = idx % HFB;
        sm.ow2[l*68 + i] = ow[((size_t)r*LB + l)*HFB + i];
    }
    if (tid < LB) sm.obS[tid] = ob_g[r*LB + tid];
    for (int idx = tid; idx < 3*HHB*LB; idx += NTHREADS) {
        int j = idx / LB, i = idx % LB;
        sm.wih2[j*36 + i] = wih[((size_t)r*3*HHB + j)*LB + i];
        sm.whh2[j*36 + i] = whh[((size_t)r*3*HHB + j)*HHB + i];
    }
    if (tid < 96) { sm.bihS[tid] = bih_g[r*96 + tid]; sm.bhhS[tid] = bhh_g[r*96 + tid]; }

    const int w    = tid >> 5;
    const int lane = tid & 31;

    // ---- init per-batch state ----
    if (w < nb) {
        const int b = b0 + w;
        #pragma unroll
        for (int rr = 0; rr < RB; rr++)
            sm.zs[w][rr][lane] = z0[((size_t)b*RB + rr)*LB + lane];
        sm.hg[w][lane] = h0[((size_t)b*RB + r)*HHB + lane];
    }
    __syncthreads();

    for (int t = 0; t < T; t++) {
        // ============ phase 0: own-state precompute (no peer deps) ==========
        if (w == 0) {
            float4 wr[8];
            #pragma unroll
            for (int q = 0; q < 8; q++) wr[q] = *(const float4*)&sm.gsw2[lane*36 + 4*q];
            for (int b = 0; b < nb; b++) {
                const float4* a4 = (const float4*)&sm.zs[b][r][0];
                float a = sm.gsb[lane], c = 0.f;
                #pragma unroll
                for (int q = 0; q < 8; q++) {
                    float4 x = wr[q], v = a4[q];
                    a = fmaf(x.x, v.x, a); c = fmaf(x.y, v.y, c);
                    a = fmaf(x.z, v.z, a); c = fmaf(x.w, v.w, c);
                }
                sm.gparts[b][lane] = a + c;
            }
        } else if (w <= 2) {
            const int row = lane + (w - 1)*32;
            float4 wr[8];
            #pragma unroll
            for (int q = 0; q < 8; q++) wr[q] = *(const float4*)&sm.lw2[row*68 + 4*q];
            for (int b = 0; b < nb; b++) {
                const float4* a4 = (const float4*)&sm.zs[b][r][0];
                float a = sm.lbS[row], c = 0.f;
                #pragma unroll
                for (int q = 0; q < 8; q++) {
                    float4 x = wr[q], v = a4[q];
                    a = fmaf(x.x, v.x, a); c = fmaf(x.y, v.y, c);
                    a = fmaf(x.z, v.z, a); c = fmaf(x.w, v.w, c);
                }
                sm.lwz[b][row] = a + c;
            }
        } else {
            const int row = lane + (w - 3)*32;
            float4 wr[8];
            #pragma unroll
            for (int q = 0; q < 8; q++) wr[q] = *(const float4*)&sm.whh2[row*36 + 4*q];
            for (int b = 0; b < nb; b++) {
                const float4* a4 = (const float4*)&sm.hg[b][0];
                float a = sm.bhhS[row], c = 0.f;
                #pragma unroll
                for (int q = 0; q < 8; q++) {
                    float4 x = wr[q], v = a4[q];
                    a = fmaf(x.x, v.x, a); c = fmaf(x.y, v.y, c);
                    a = fmaf(x.z, v.z, a); c = fmaf(x.w, v.w, c);
                }
                sm.ghS[b][row] = a + c;
            }
        }

        // ============ poll for peers' z(t-1), then load ============
        if (t > 0 && w < nb) {
            const unsigned need = (unsigned)t;
            for (;;) {
                unsigned v = need;
                if (lane < RB) v = ld_acquire(&g_flag[g][w][lane]);
                if (__all_sync(0xffffffffu, v >= need)) break;
            }
            const float* zsrc = zt + ((size_t)(b0 + w)*T + (t - 1))*RB*LB;
            #pragma unroll
            for (int rr = 0; rr < RB; rr++) {
                if (rr != r)
                    sm.zs[w][rr][lane] = __ldcg(&zsrc[rr*LB + lane]);
            }
        }
        __syncthreads();

        // ============ phase 1: edge messages (mean) ============
        {
            const int sub = lane >> 4, m16 = lane & 15;
            const int s0 = 2*w + sub;
            const bool act = (s0 < 11);
            float4 wr[8];
            float bias = 0.f; int sL = 0; size_t eoff = 0;
            if (act) {
                #pragma unroll
                for (int q = 0; q < 8; q++) wr[q] = *(const float4*)&sm.mw2[(s0*16 + m16)*36 + 4*q];
                bias = sm.mb[s0*16 + m16];
                sL = sm.slist[s0];
                eoff = (size_t)sm.elist[s0]*MB + m16;
            }
            for (int b = 0; b < nb; b++) {
                if (act) {
                    const float4* a4 = (const float4*)&sm.zs[b][sL][0];
                    float a = bias, c = 0.f;
                    #pragma unroll
                    for (int q = 0; q < 8; q++) {
                        float4 x = wr[q], v = a4[q];
                        a = fmaf(x.x, v.x, a); c = fmaf(x.y, v.y, c);
                        a = fmaf(x.z, v.z, a); c = fmaf(x.w, v.w, c);
                    }
                    const float mv = a + c;
                    sm.meanS[b][s0][m16] = mv;
                    ms[((size_t)(b0 + b)*T + t)*(EB*MB) + eoff] = mv;
                }
            }
        }
        __syncthreads();

        // ============ phase 2: add-projection partials ============
        {
            const int sA = 2*w, sB = 2*w + 1;
            const bool hasB = (sB < 11);
            float4 wa[4], wbr[4];
            #pragma unroll
            for (int q = 0; q < 4; q++) wa[q] = *(const float4*)&sm.aw2[(sA*32 + lane)*20 + 4*q];
            if (hasB) {
                #pragma unroll
                for (int q = 0; q < 4; q++) wbr[q] = *(const float4*)&sm.aw2[(sB*32 + lane)*20 + 4*q];
            }
            for (int b = 0; b < nb; b++) {
                float a = 0.f, c = 0.f;
                const float4* aA = (const float4*)&sm.meanS[b][sA][0];
                #pragma unroll
                for (int q = 0; q < 4; q++) {
                    float4 x = wa[q], v = aA[q];
                    a = fmaf(x.x, v.x, a); c = fmaf(x.y, v.y, c);
                    a = fmaf(x.z, v.z, a); c = fmaf(x.w, v.w, c);
                }
                if (hasB) {
                    const float4* aB = (const float4*)&sm.meanS[b][sB][0];
                    #pragma unroll
                    for (int q = 0; q < 4; q++) {
                        float4 x = wbr[q], v = aB[q];
                        a = fmaf(x.x, v.x, a); c = fmaf(x.y, v.y, c);
                        a = fmaf(x.z, v.z, a); c = fmaf(x.w, v.w, c);
                    }
                }
                sm.part[w][b][lane] = a + c;
            }
        }
        __syncthreads();

        // ============ phase 3: reduce partials -> inc ============
        if (w < nb) {
            float s = (sm.part[0][w][lane] + sm.part[1][w][lane])
                    + (sm.part[2][w][lane] + sm.part[3][w][lane])
                    + (sm.part[4][w][lane] + sm.part[5][w][lane]);
            sm.incS[w][lane] = s;
        }
        __syncthreads();

        // ============ phase 4: inc-dependent matvecs ============
        if (w == 0) {
            float4 wr[8];
            #pragma unroll
            for (int q = 0; q < 8; q++) wr[q] = *(const float4*)&sm.gcw2[lane*36 + 4*q];
            for (int b = 0; b < nb; b++) {
                const float4* a4 = (const float4*)&sm.incS[b][0];
                float a = sm.gparts[b][lane], c = 0.f;
                #pragma unroll
                for (int q = 0; q < 8; q++) {
                    float4 x = wr[q], v = a4[q];
                    a = fmaf(x.x, v.x, a); c = fmaf(x.y, v.y, c);
                    a = fmaf(x.z, v.z, a); c = fmaf(x.w, v.w, c);
                }
                sm.gateS[b][lane] = fsig(a + c);
            }
        } else if (w <= 2) {
            const int row = lane + (w - 1)*32;
            float4 wr[8];
            #pragma unroll
            for (int q = 0; q < 8; q++) wr[q] = *(const float4*)&sm.lw2[row*68 + 32 + 4*q];
            for (int b = 0; b < nb; b++) {
                const float4* a4 = (const float4*)&sm.incS[b][0];
                float a = sm.lwz[b][row], c = 0.f;
                #pragma unroll
                for (int q = 0; q < 8; q++) {
                    float4 x = wr[q], v = a4[q];
                    a = fmaf(x.x, v.x, a); c = fmaf(x.y, v.y, c);
                    a = fmaf(x.z, v.z, a); c = fmaf(x.w, v.w, c);
                }
                const float v2 = a + c;
                sm.hbuf[b][row] = v2 * fsig(v2);
            }
        } else {
            const int row = lane + (w - 3)*32;
            float4 wr[8];
            #pragma unroll
            for (int q = 0; q < 8; q++) wr[q] = *(const float4*)&sm.wih2[row*36 + 4*q];
            for (int b = 0; b < nb; b++) {
                const float4* a4 = (const float4*)&sm.incS[b][0];
                float a = sm.bihS[row], c = 0.f;
                #pragma unroll
                for (int q = 0; q < 8; q++) {
                    float4 x = wr[q], v = a4[q];
                    a = fmaf(x.x, v.x, a); c = fmaf(x.y, v.y, c);
                    a = fmaf(x.z, v.z, a); c = fmaf(x.w, v.w, c);
                }
                sm.giS[b][row] = a + c;
            }
        }
        __syncthreads();

        // ============ phase 5: out layer + z update + publish; phase 6: GRU ==
        if (w < nb) {
            float4 wr[16];
            #pragma unroll
            for (int q = 0; q < 16; q++) wr[q] = *(const float4*)&sm.ow2[lane*68 + 4*q];
            const float4* a4 = (const float4*)&sm.hbuf[w][0];
            float a = sm.obS[lane], c = 0.f, d = 0.f, e = 0.f;
            #pragma unroll
            for (int q = 0; q < 16; q++) {
                float4 x = wr[q], v = a4[q];
                a = fmaf(x.x, v.x, a); c = fmaf(x.y, v.y, c);
                d = fmaf(x.z, v.z, d); e = fmaf(x.w, v.w, e);
            }
            const float target = tanhf((a + c) + (d + e));
            const float zold = sm.zs[w][r][lane];
            const float znew = fmaf(0.1f * sm.gateS[w][lane], target - zold, zold);
            zt[(((size_t)(b0 + w)*T + t)*RB + r)*LB + lane] = znew;
            sm.zs[w][r][lane] = znew;
            __syncwarp();
            if (lane == 0) {
                __threadfence();
                st_release(&g_flag[g][w][r], (unsigned)(t + 1));
            }
            // GRU finalize (off inter-block critical path)
            const float gr = fsig(sm.giS[w][lane]      + sm.ghS[w][lane]);
            const float gz = fsig(sm.giS[w][32 + lane] + sm.ghS[w][32 + lane]);
            const float nn = tanhf(fmaf(gr, sm.ghS[w][64 + lane], sm.giS[w][64 + lane]));
            const float hold = sm.hg[w][lane];
            sm.hg[w][lane] = (1.0f - gz)*nn + gz*hold;
        }
        __syncthreads();
    }

    if (w < nb)
        hf[((size_t)(b0 + w)*RB + r)*HHB + lane] = sm.hg[w][lane];
}

extern "C" void kernel_launch(void* const* d_in, const int* in_sizes, int n_in,
                              void* d_out, int out_size) {
    const float* z0     = (const float*)d_in[0];
    const float* h0     = (const float*)d_in[1];
    const float* mean_w = (const float*)d_in[2];
    const float* mean_b = (const float*)d_in[3];
    const float* add_w  = (const float*)d_in[4];
    const float* gsw    = (const float*)d_in[5];
    const float* gsb    = (const float*)d_in[6];
    const float* gcw    = (const float*)d_in[7];
    const float* lw     = (const float*)d_in[8];
    const float* lb     = (const float*)d_in[9];
    const float* ow     = (const float*)d_in[10];
    const float* ob     = (const float*)d_in[11];
    const float* wih    = (const float*)d_in[12];
    const float* whh    = (const float*)d_in[13];
    const float* bih    = (const float*)d_in[14];
    const float* bhh    = (const float*)d_in[15];
    const int* src_idx  = (const int*)d_in[16];
    const int* tgt_idx  = (const int*)d_in[17];
    // out_size = B*T*R*L + B*R*Hh + B*T*E*M
    const int per_t = BTOT*RB*LB + BTOT*EB*MB;
    const int T = (out_size - BTOT*RB*HHB) / per_t;

    float* out = (float*)d_out;
    float* zt = out;
    float* hf = zt + (size_t)BTOT * T * RB * LB;
    float* ms = hf + (size_t)BTOT * RB * HHB;

    cudaFuncSetAttribute(nv_main_kernel,
                         cudaFuncAttributeMaxDynamicSharedMemorySize,
                         (int)sizeof(SmemLayout));

    nv_init_kernel<<<1, 256>>>();
    nv_main_kernel<<<NBLOCKS, NTHREADS, sizeof(SmemLayout)>>>(
        z0, h0, mean_w, mean_b, add_w, gsw, gsb, gcw, lw, lb, ow, ob,
        wih, whh, bih, bhh, src_idx, tgt_idx, T, zt, hf, ms);
}

// round 4
// speedup vs baseline: 1.0979x; 1.0979x over previous
#include <cuda_runtime.h>
#include <cstddef>

// Problem constants (fixed by setup_inputs)
#define RB   12
#define LB   32
#define MB   16
#define HHB  32
#define HFB  64
#define EB   132
#define BTOT 64
#define NGROUP 12
#define NBLOCKS (NGROUP*RB)
#define NTHREADS 384   // 12 warps = 6 pairs
#define MAXWB 6

__device__ unsigned g_flag[NGROUP][MAXWB][RB];

struct __align__(16) SmemLayout {
    // weights, row-per-output, padded strides (conflict-free LDS.128)
    float mw2[11*16*36];   // [slot][m][k] stride 36
    float aw2[11*32*20];   // [slot][l][m] stride 20
    float mb [11*16];
    float gsw2[32*36];     // [o][i]
    float gcw2[32*36];
    float gsb[32];
    float lw2[64*68];      // [o][i0..63]
    float lbS[64];
    float ow2[32*68];      // [l][hf]
    float obS[32];
    float wih2[96*36];     // [j][i]
    float whh2[96*36];
    float bihS[96];
    float bhhS[96];
    // activations (per batch)
    float zs   [MAXWB][RB][LB];
    float meanS[MAXWB][11][MB];
    float part [2][MAXWB][LB];
    float gparts[MAXWB][LB];
    float gateS[MAXWB][LB];
    float hbuf [MAXWB][HFB];
    float hg   [MAXWB][HHB];
    int   elist[12];
    int   slist[12];
};

__device__ __forceinline__ float fsig(float x) { return 1.0f / (1.0f + __expf(-x)); }

__device__ __forceinline__ void st_release(unsigned* p, unsigned v) {
    asm volatile("st.release.gpu.u32 [%0], %1;" :: "l"(p), "r"(v) : "memory");
}
__device__ __forceinline__ unsigned ld_acquire(unsigned* p) {
    unsigned v;
    asm volatile("ld.acquire.gpu.u32 %0, [%1];" : "=r"(v) : "l"(p) : "memory");
    return v;
}
__device__ __forceinline__ void pair_bar(int id) {
    asm volatile("bar.sync %0, 64;" :: "r"(id) : "memory");
}

__global__ void nv_init_kernel() {
    unsigned* p = &g_flag[0][0][0];
    const int n = NGROUP*MAXWB*RB;
    for (int i = threadIdx.x; i < n; i += blockDim.x) p[i] = 0u;
}

__global__ void __launch_bounds__(NTHREADS, 1) nv_main_kernel(
    const float* __restrict__ z0,  const float* __restrict__ h0,
    const float* __restrict__ mean_w, const float* __restrict__ mean_b,
    const float* __restrict__ add_w,
    const float* __restrict__ gsw, const float* __restrict__ gsb_g,
    const float* __restrict__ gcw,
    const float* __restrict__ lw,  const float* __restrict__ lb_g,
    const float* __restrict__ ow,  const float* __restrict__ ob_g,
    const float* __restrict__ wih, const float* __restrict__ whh,
    const float* __restrict__ bih_g, const float* __restrict__ bhh_g,
    const int* __restrict__ src_idx, const int* __restrict__ tgt_idx,
    int T,
    float* __restrict__ zt, float* __restrict__ hf, float* __restrict__ ms)
{
    extern __shared__ char smraw[];
    SmemLayout& sm = *reinterpret_cast<SmemLayout*>(smraw);
    const int tid = threadIdx.x;
    const int g = blockIdx.x / RB;
    const int r = blockIdx.x % RB;

    const int nb = (g < 4) ? 6 : 5;
    const int b0 = g * 5 + (g < 4 ? g : 4);

    // ---- incoming-edge list for region r ----
    for (int e = tid; e < EB; e += NTHREADS) {
        if (tgt_idx[e] == r) {
            int s = src_idx[e];
            int slot = (s < r) ? s : s - 1;
            sm.elist[slot] = e;
            sm.slist[slot] = s;
        }
    }
    __syncthreads();

    // ---- cache weights to smem ----
    for (int idx = tid; idx < 11*MB*LB; idx += NTHREADS) {
        int slot = idx / (MB*LB); int rem = idx % (MB*LB);
        int m = rem / LB, k = rem % LB;
        int e = sm.elist[slot];
        sm.mw2[(slot*16 + m)*36 + k] = mean_w[((size_t)e*MB + m)*LB + k];
    }
    for (int idx = tid; idx < 11*LB*MB; idx += NTHREADS) {
        int slot = idx / (LB*MB); int rem = idx % (LB*MB);
        int l = rem / MB, m = rem % MB;
        int e = sm.elist[slot];
        sm.aw2[(slot*32 + l)*20 + m] = add_w[((size_t)e*LB + l)*MB + m];
    }
    for (int idx = tid; idx < 11*MB; idx += NTHREADS) {
        int slot = idx / MB, m = idx % MB;
        sm.mb[idx] = mean_b[sm.elist[slot]*MB + m];
    }
    for (int idx = tid; idx < LB*LB; idx += NTHREADS) {
        int o = idx / LB, i = idx % LB;
        sm.gsw2[o*36 + i] = gsw[((size_t)r*LB + o)*LB + i];
        sm.gcw2[o*36 + i] = gcw[((size_t)r*LB + o)*LB + i];
    }
    if (tid < LB) sm.gsb[tid] = gsb_g[r*LB + tid];
    for (int idx = tid; idx < HFB*2*LB; idx += NTHREADS) {
        int o = idx / (2*LB), i = idx % (2*LB);
        sm.lw2[o*68 + i] = lw[((size_t)r*HFB + o)*(2*LB) + i];
    }
    if (tid < HFB) sm.lbS[tid] = lb_g[r*HFB + tid];
    for (int idx = tid; idx < LB*HFB; idx += NTHREADS) {
        int l = idx / HFB, i = idx % HFB;
        sm.ow2[l*68 + i] = ow[((size_t)r*LB + l)*HFB + i];
    }
    if (tid < LB) sm.obS[tid] = ob_g[r*LB + tid];
    for (int idx = tid; idx < 3*HHB*LB; idx += NTHREADS) {
        int j = idx / LB, i = idx % LB;
        sm.wih2[j*36 + i] = wih[((size_t)r*3*HHB + j)*LB + i];
        sm.whh2[j*36 + i] = whh[((size_t)r*3*HHB + j)*HHB + i];
    }
    if (tid < 96) { sm.bihS[tid] = bih_g[r*96 + tid]; sm.bhhS[tid] = bhh_g[r*96 + tid]; }

    const int w    = tid >> 5;
    const int lane = tid & 31;
    const int p    = w >> 1;     // pair = batch slot
    const int u    = w & 1;      // role within pair

    // ---- init per-batch state (u0 of each pair) ----
    if (p < nb && u == 0) {
        const int b = b0 + p;
        #pragma unroll
        for (int rr = 0; rr < RB; rr++)
            sm.zs[p][rr][lane] = z0[((size_t)b*RB + rr)*LB + lane];
        sm.hg[p][lane] = h0[((size_t)b*RB + r)*HHB + lane];
    }
    __syncthreads();
    if (p >= nb) return;

    const int b = b0 + p;
    const int barid = 1 + p;
    const int sub = lane >> 4, m16 = lane & 15;

    float hnew = 0.0f;

    for (int t = 0; t < T; t++) {
        // =========== phase A: own-state precompute (no peer deps) ===========
        float gh0 = 0.f, gh1 = 0.f, gh2 = 0.f;      // u0: whh gates
        float pz0 = 0.f, pz1 = 0.f;                 // u1: lw z-half
        if (u == 0) {
            float a0 = sm.bhhS[lane],      c0 = 0.f;
            float a1 = sm.bhhS[32 + lane], c1 = 0.f;
            float a2 = sm.bhhS[64 + lane], c2 = 0.f;
            const float4* h4 = (const float4*)&sm.hg[p][0];
            const float4* w0 = (const float4*)&sm.whh2[(lane     )*36];
            const float4* w1 = (const float4*)&sm.whh2[(lane + 32)*36];
            const float4* w2 = (const float4*)&sm.whh2[(lane + 64)*36];
            #pragma unroll
            for (int q = 0; q < 8; q++) {
                float4 a = h4[q];
                float4 x0 = w0[q], x1 = w1[q], x2 = w2[q];
                a0 = fmaf(x0.x, a.x, a0); c0 = fmaf(x0.y, a.y, c0);
                a0 = fmaf(x0.z, a.z, a0); c0 = fmaf(x0.w, a.w, c0);
                a1 = fmaf(x1.x, a.x, a1); c1 = fmaf(x1.y, a.y, c1);
                a1 = fmaf(x1.z, a.z, a1); c1 = fmaf(x1.w, a.w, c1);
                a2 = fmaf(x2.x, a.x, a2); c2 = fmaf(x2.y, a.y, c2);
                a2 = fmaf(x2.z, a.z, a2); c2 = fmaf(x2.w, a.w, c2);
            }
            gh0 = a0 + c0; gh1 = a1 + c1; gh2 = a2 + c2;
        } else {
            // lw z-half (rows lane, lane+32) + gsw -> gparts
            float a0 = sm.lbS[lane],      c0 = 0.f;
            float a1 = sm.lbS[lane + 32], c1 = 0.f;
            float ag = sm.gsb[lane],      cg = 0.f;
            const float4* z4 = (const float4*)&sm.zs[p][r][0];
            const float4* w0 = (const float4*)&sm.lw2[(lane     )*68];
            const float4* w1 = (const float4*)&sm.lw2[(lane + 32)*68];
            const float4* wg = (const float4*)&sm.gsw2[lane*36];
            #pragma unroll
            for (int q = 0; q < 8; q++) {
                float4 a = z4[q];
                float4 x0 = w0[q], x1 = w1[q], xg = wg[q];
                a0 = fmaf(x0.x, a.x, a0); c0 = fmaf(x0.y, a.y, c0);
                a0 = fmaf(x0.z, a.z, a0); c0 = fmaf(x0.w, a.w, c0);
                a1 = fmaf(x1.x, a.x, a1); c1 = fmaf(x1.y, a.y, c1);
                a1 = fmaf(x1.z, a.z, a1); c1 = fmaf(x1.w, a.w, c1);
                ag = fmaf(xg.x, a.x, ag); cg = fmaf(xg.y, a.y, cg);
                ag = fmaf(xg.z, a.z, ag); cg = fmaf(xg.w, a.w, cg);
            }
            pz0 = a0 + c0; pz1 = a1 + c1;
            sm.gparts[p][lane] = ag + cg;
        }

        // =========== poll peers' z(t-1), load the srcs THIS warp needs ======
        if (t > 0) {
            const unsigned need = (unsigned)t;
            for (;;) {
                unsigned v = need;
                if (lane < RB) v = ld_acquire(&g_flag[g][p][lane]);
                if (__all_sync(0xffffffffu, v >= need)) break;
            }
            const float* zsrc = zt + ((size_t)b*T + (t - 1))*RB*LB;
            const int k0 = u*6, k1 = u ? 11 : 6;
            for (int k = k0; k < k1; k++) {
                const int rr = sm.slist[k];
                sm.zs[p][rr][lane] = __ldcg(&zsrc[rr*LB + lane]);
            }
            __syncwarp();
        }

        // =========== edges: mean + projection partials (per-warp slots) =====
        float inc0 = 0.f, inc1 = 0.f, inc2 = 0.f, inc3 = 0.f;
        float* msbase = ms + ((size_t)b*T + t)*(EB*MB);
        #pragma unroll
        for (int rd = 0; rd < 3; rd++) {
            const int base = u*6 + 2*rd;
            const int slot = base + sub;
            if (slot < 11) {
                const int s = sm.slist[slot];
                const float4* w4 = (const float4*)&sm.mw2[(slot*16 + m16)*36];
                const float4* a4 = (const float4*)&sm.zs[p][s][0];
                float a = sm.mb[slot*16 + m16], c = 0.f;
                #pragma unroll
                for (int q = 0; q < 8; q++) {
                    float4 x = w4[q], v = a4[q];
                    a = fmaf(x.x, v.x, a); c = fmaf(x.y, v.y, c);
                    a = fmaf(x.z, v.z, a); c = fmaf(x.w, v.w, c);
                }
                const float mv = a + c;
                sm.meanS[p][slot][m16] = mv;
                msbase[(size_t)sm.elist[slot]*MB + m16] = mv;
            }
            __syncwarp();
            const int n2 = (base + 1 < 11) ? 2 : 1;
            for (int ss = 0; ss < n2; ss++) {
                const float4* w4 = (const float4*)&sm.aw2[((base + ss)*32 + lane)*20];
                const float4* a4 = (const float4*)&sm.meanS[p][base + ss][0];
                #pragma unroll
                for (int q = 0; q < 4; q++) {
                    float4 x = w4[q], v = a4[q];
                    inc0 = fmaf(x.x, v.x, inc0); inc1 = fmaf(x.y, v.y, inc1);
                    inc2 = fmaf(x.z, v.z, inc2); inc3 = fmaf(x.w, v.w, inc3);
                }
            }
        }
        sm.part[u][p][lane] = (inc0 + inc1) + (inc2 + inc3);
        pair_bar(barid);     // partials + gparts visible to both warps

        // avec = part0 + part1 (registers)
        float4 av[8];
        {
            const float4* p0 = (const float4*)&sm.part[0][p][0];
            const float4* p1 = (const float4*)&sm.part[1][p][0];
            #pragma unroll
            for (int q = 0; q < 8; q++) {
                float4 x = p0[q], y = p1[q];
                av[q].x = x.x + y.x; av[q].y = x.y + y.y;
                av[q].z = x.z + y.z; av[q].w = x.w + y.w;
            }
        }

        if (u == 0) {
            // ---- gcw -> gate (publish to u1), then wih + GRU ----
            float ag = sm.gparts[p][lane], cg = 0.f;
            {
                const float4* wg = (const float4*)&sm.gcw2[lane*36];
                #pragma unroll
                for (int q = 0; q < 8; q++) {
                    float4 x = wg[q], a = av[q];
                    ag = fmaf(x.x, a.x, ag); cg = fmaf(x.y, a.y, cg);
                    ag = fmaf(x.z, a.z, ag); cg = fmaf(x.w, a.w, cg);
                }
            }
            sm.gateS[p][lane] = fsig(ag + cg);
            pair_bar(barid);

            float a0 = sm.bihS[lane],      c0 = 0.f;
            float a1 = sm.bihS[32 + lane], c1 = 0.f;
            float a2 = sm.bihS[64 + lane], c2 = 0.f;
            const float4* w0 = (const float4*)&sm.wih2[(lane     )*36];
            const float4* w1 = (const float4*)&sm.wih2[(lane + 32)*36];
            const float4* w2 = (const float4*)&sm.wih2[(lane + 64)*36];
            #pragma unroll
            for (int q = 0; q < 8; q++) {
                float4 a = av[q];
                float4 x0 = w0[q], x1 = w1[q], x2 = w2[q];
                a0 = fmaf(x0.x, a.x, a0); c0 = fmaf(x0.y, a.y, c0);
                a0 = fmaf(x0.z, a.z, a0); c0 = fmaf(x0.w, a.w, c0);
                a1 = fmaf(x1.x, a.x, a1); c1 = fmaf(x1.y, a.y, c1);
                a1 = fmaf(x1.z, a.z, a1); c1 = fmaf(x1.w, a.w, c1);
                a2 = fmaf(x2.x, a.x, a2); c2 = fmaf(x2.y, a.y, c2);
                a2 = fmaf(x2.z, a.z, a2); c2 = fmaf(x2.w, a.w, c2);
            }
            const float gr = fsig((a0 + c0) + gh0);
            const float gz = fsig((a1 + c1) + gh1);
            const float nn = tanhf(fmaf(gr, gh2, (a2 + c2)));
            const float hold = sm.hg[p][lane];
            hnew = (1.0f - gz)*nn + gz*hold;
            sm.hg[p][lane] = hnew;
            __syncwarp();
        } else {
            // ---- lw inc-half -> hbuf, then ow -> znew, publish ----
            float a0 = pz0, c0 = 0.f;
            float a1 = pz1, c1 = 0.f;
            {
                const float4* w0 = (const float4*)&sm.lw2[(lane     )*68 + 32/4*4 + 32];
                const float4* w1 = (const float4*)&sm.lw2[(lane + 32)*68 + 32];
                const float4* w0f = (const float4*)&sm.lw2[(lane     )*68 + 32];
                #pragma unroll
                for (int q = 0; q < 8; q++) {
                    float4 a = av[q];
                    float4 x0 = w0f[q], x1 = w1[q];
                    a0 = fmaf(x0.x, a.x, a0); c0 = fmaf(x0.y, a.y, c0);
                    a0 = fmaf(x0.z, a.z, a0); c0 = fmaf(x0.w, a.w, c0);
                    a1 = fmaf(x1.x, a.x, a1); c1 = fmaf(x1.y, a.y, c1);
                    a1 = fmaf(x1.z, a.z, a1); c1 = fmaf(x1.w, a.w, c1);
                }
                (void)w0;
            }
            const float v0 = a0 + c0, v1 = a1 + c1;
            sm.hbuf[p][lane]      = v0 * fsig(v0);
            sm.hbuf[p][lane + 32] = v1 * fsig(v1);
            pair_bar(barid);

            float ta = sm.obS[lane], tb = 0.f, tc = 0.f, td = 0.f;
            {
                const float4* w4 = (const float4*)&sm.ow2[lane*68];
                const float4* a4 = (const float4*)&sm.hbuf[p][0];
                #pragma unroll
                for (int q = 0; q < 16; q++) {
                    float4 x = w4[q], a = a4[q];
                    ta = fmaf(x.x, a.x, ta); tb = fmaf(x.y, a.y, tb);
                    tc = fmaf(x.z, a.z, tc); td = fmaf(x.w, a.w, td);
                }
            }
            const float target = tanhf((ta + tb) + (tc + td));
            const float zold = sm.zs[p][r][lane];
            const float znew = fmaf(0.1f * sm.gateS[p][lane], target - zold, zold);
            zt[(((size_t)b*T + t)*RB + r)*LB + lane] = znew;
            sm.zs[p][r][lane] = znew;
            __syncwarp();
            if (lane == 0) {
                __threadfence();
                st_release(&g_flag[g][p][r], (unsigned)(t + 1));
            }
        }
    }

    if (u == 0)
        hf[((size_t)b*RB + r)*HHB + lane] = hnew;
}

extern "C" void kernel_launch(void* const* d_in, const int* in_sizes, int n_in,
                              void* d_out, int out_size) {
    const float* z0     = (const float*)d_in[0];
    const float* h0     = (const float*)d_in[1];
    const float* mean_w = (const float*)d_in[2];
    const float* mean_b = (const float*)d_in[3];
    const float* add_w  = (const float*)d_in[4];
    const float* gsw    = (const float*)d_in[5];
    const float* gsb    = (const float*)d_in[6];
    const float* gcw    = (const float*)d_in[7];
    const float* lw     = (const float*)d_in[8];
    const float* lb     = (const float*)d_in[9];
    const float* ow     = (const float*)d_in[10];
    const float* ob     = (const float*)d_in[11];
    const float* wih    = (const float*)d_in[12];
    const float* whh    = (const float*)d_in[13];
    const float* bih    = (const float*)d_in[14];
    const float* bhh    = (const float*)d_in[15];
    const int* src_idx  = (const int*)d_in[16];
    const int* tgt_idx  = (const int*)d_in[17];
    // out_size = B*T*R*L + B*R*Hh + B*T*E*M
    const int per_t = BTOT*RB*LB + BTOT*EB*MB;
    const int T = (out_size - BTOT*RB*HHB) / per_t;

    float* out = (float*)d_out;
    float* zt = out;
    float* hf = zt + (size_t)BTOT * T * RB * LB;
    float* ms = hf + (size_t)BTOT * RB * HHB;

    cudaFuncSetAttribute(nv_main_kernel,
                         cudaFuncAttributeMaxDynamicSharedMemorySize,
                         (int)sizeof(SmemLayout));

    nv_init_kernel<<<1, 256>>>();
    nv_main_kernel<<<NBLOCKS, NTHREADS, sizeof(SmemLayout)>>>(
        z0, h0, mean_w, mean_b, add_w, gsw, gsb, gcw, lw, lb, ow, ob,
        wih, whh, bih, bhh, src_idx, tgt_idx, T, zt, hf, ms);
}

// round 5
// speedup vs baseline: 1.5794x; 1.4386x over previous
#include <cuda_runtime.h>
#include <cstddef>
#include <cstdint>

// Problem constants (fixed by setup_inputs)
#define RB   12
#define LB   32
#define MB   16
#define HHB  32
#define HFB  64
#define EB   132
#define BTOT 64
#define NGROUP 8          // 8 groups x 8 batches
#define NB_PER 8
#define NBLOCKS (NGROUP*RB)   // 96 blocks = 8 clusters of 12
#define NTHREADS 256          // 8 warps, one batch each

struct __align__(16) SmemLayout {
    unsigned long long mbar[NB_PER][2];   // per-warp, alternating by step
    // weights, row-per-output, padded strides (conflict-free LDS.128)
    float mw2[11*16*36];   // [slot][m][k] stride 36
    float aw2[11*32*20];   // [slot][l][m] stride 20
    float mb [11*16];
    float gsw2[32*36];     // [o][i]
    float gcw2[32*36];
    float gsb[32];
    float lw2[64*68];      // [o][i0..63]
    float lbS[64];
    float ow2[32*68];      // [l][hf]
    float obS[32];
    float wih2[96*36];     // [j][i]
    float whh2[96*36];
    float bihS[96];
    float bhhS[96];
    // activations
    float zsD [2][NB_PER][RB][LB];   // double-buffered z, peers write via DSMEM
    float meanS[NB_PER][2][MB];
    float incS [NB_PER][LB];
    float hbuf [NB_PER][HFB];
    float hg   [NB_PER][HHB];
    int   elist[12];
    int   slist[12];
};

__device__ __forceinline__ float fsig(float x) { return 1.0f / (1.0f + __expf(-x)); }

__device__ __forceinline__ uint32_t smem_u32(const void* p) {
    uint32_t a;
    asm("{ .reg .u64 t; cvta.to.shared.u64 t, %1; cvt.u32.u64 %0, t; }"
        : "=r"(a) : "l"(p));
    return a;
}
__device__ __forceinline__ uint32_t mapa_rank(uint32_t laddr, uint32_t rank) {
    uint32_t r;
    asm("mapa.shared::cluster.u32 %0, %1, %2;" : "=r"(r) : "r"(laddr), "r"(rank));
    return r;
}
__device__ __forceinline__ void st_remote_f32(uint32_t addr, float v) {
    asm volatile("st.shared::cluster.f32 [%0], %1;" :: "r"(addr), "f"(v) : "memory");
}
__device__ __forceinline__ void mbar_arrive_remote(uint32_t addr) {
    asm volatile("mbarrier.arrive.release.cluster.shared::cluster.b64 _, [%0];"
                 :: "r"(addr) : "memory");
}
__device__ __forceinline__ void mbar_init(uint32_t addr, uint32_t cnt) {
    asm volatile("mbarrier.init.shared.b64 [%0], %1;" :: "r"(addr), "r"(cnt) : "memory");
}
__device__ __forceinline__ void mbar_wait(uint32_t addr, uint32_t parity) {
    uint32_t done;
    do {
        asm volatile(
            "{\n\t.reg .pred p;\n\t"
            "mbarrier.try_wait.parity.acquire.cluster.shared::cta.b64 p, [%1], %2, 0x989680;\n\t"
            "selp.b32 %0, 1, 0, p;\n\t}"
            : "=r"(done) : "r"(addr), "r"(parity) : "memory");
    } while (!done);
}
__device__ __forceinline__ void cluster_sync_all() {
    asm volatile("barrier.cluster.arrive.aligned;" ::: "memory");
    asm volatile("barrier.cluster.wait.aligned;" ::: "memory");
}

__global__ void __launch_bounds__(NTHREADS, 1) __cluster_dims__(RB, 1, 1)
nv_main_kernel(
    const float* __restrict__ z0,  const float* __restrict__ h0,
    const float* __restrict__ mean_w, const float* __restrict__ mean_b,
    const float* __restrict__ add_w,
    const float* __restrict__ gsw, const float* __restrict__ gsb_g,
    const float* __restrict__ gcw,
    const float* __restrict__ lw,  const float* __restrict__ lb_g,
    const float* __restrict__ ow,  const float* __restrict__ ob_g,
    const float* __restrict__ wih, const float* __restrict__ whh,
    const float* __restrict__ bih_g, const float* __restrict__ bhh_g,
    const int* __restrict__ src_idx, const int* __restrict__ tgt_idx,
    int T,
    float* __restrict__ zt, float* __restrict__ hf, float* __restrict__ ms)
{
    extern __shared__ char smraw[];
    SmemLayout& sm = *reinterpret_cast<SmemLayout*>(smraw);
    const int tid = threadIdx.x;
    const int g = blockIdx.x / RB;
    const int r = blockIdx.x % RB;
    const int b0 = g * NB_PER;

    // ---- incoming-edge list for region r ----
    for (int e = tid; e < EB; e += NTHREADS) {
        if (tgt_idx[e] == r) {
            int s = src_idx[e];
            int slot = (s < r) ? s : s - 1;
            sm.elist[slot] = e;
            sm.slist[slot] = s;
        }
    }
    // ---- mbarrier init ----
    if (tid < NB_PER*2) mbar_init(smem_u32(&sm.mbar[tid >> 1][tid & 1]), 11);
    __syncthreads();

    // ---- cache weights to smem ----
    for (int idx = tid; idx < 11*MB*LB; idx += NTHREADS) {
        int slot = idx / (MB*LB); int rem = idx % (MB*LB);
        int m = rem / LB, k = rem % LB;
        int e = sm.elist[slot];
        sm.mw2[(slot*16 + m)*36 + k] = mean_w[((size_t)e*MB + m)*LB + k];
    }
    for (int idx = tid; idx < 11*LB*MB; idx += NTHREADS) {
        int slot = idx / (LB*MB); int rem = idx % (LB*MB);
        int l = rem / MB, m = rem % MB;
        int e = sm.elist[slot];
        sm.aw2[(slot*32 + l)*20 + m] = add_w[((size_t)e*LB + l)*MB + m];
    }
    for (int idx = tid; idx < 11*MB; idx += NTHREADS) {
        int slot = idx / MB, m = idx % MB;
        sm.mb[idx] = mean_b[sm.elist[slot]*MB + m];
    }
    for (int idx = tid; idx < LB*LB; idx += NTHREADS) {
        int o = idx / LB, i = idx % LB;
        sm.gsw2[o*36 + i] = gsw[((size_t)r*LB + o)*LB + i];
        sm.gcw2[o*36 + i] = gcw[((size_t)r*LB + o)*LB + i];
    }
    if (tid < LB) sm.gsb[tid] = gsb_g[r*LB + tid];
    for (int idx = tid; idx < HFB*2*LB; idx += NTHREADS) {
        int o = idx / (2*LB), i = idx % (2*LB);
        sm.lw2[o*68 + i] = lw[((size_t)r*HFB + o)*(2*LB) + i];
    }
    if (tid < HFB) sm.lbS[tid] = lb_g[r*HFB + tid];
    for (int idx = tid; idx < LB*HFB; idx += NTHREADS) {
        int l = idx / HFB, i = idx % HFB;
        sm.ow2[l*68 + i] = ow[((size_t)r*LB + l)*HFB + i];
    }
    if (tid < LB) sm.obS[tid] = ob_g[r*LB + tid];
    for (int idx = tid; idx < 3*HHB*LB; idx += NTHREADS) {
        int j = idx / LB, i = idx % LB;
        sm.wih2[j*36 + i] = wih[((size_t)r*3*HHB + j)*LB + i];
        sm.whh2[j*36 + i] = whh[((size_t)r*3*HHB + j)*HHB + i];
    }
    if (tid < 96) { sm.bihS[tid] = bih_g[r*96 + tid]; sm.bhhS[tid] = bhh_g[r*96 + tid]; }

    const int w    = tid >> 5;
    const int lane = tid & 31;
    const int b    = b0 + w;
    const int sub  = lane >> 4, m16 = lane & 15;

    // ---- init per-batch state into buffer 0 ----
    {
        #pragma unroll
        for (int rr = 0; rr < RB; rr++)
            sm.zsD[0][w][rr][lane] = z0[((size_t)b*RB + rr)*LB + lane];
        sm.hg[w][lane] = h0[((size_t)b*RB + r)*HHB + lane];
    }
    __syncthreads();
    cluster_sync_all();   // mbarriers + initial state visible cluster-wide

    // ---- precompute DSMEM peer address deltas ----
    const uint32_t smem_base = smem_u32(smraw);
    uint32_t pdelta[11];
    #pragma unroll
    for (int k = 0; k < 11; k++) {
        uint32_t prank = (uint32_t)(k + (k >= r ? 1 : 0));
        pdelta[k] = mapa_rank(smem_base, prank) - smem_base;
    }
    uint32_t laneDelta = (lane < 11) ? pdelta[0] : 0u;
    {   // per-lane delta for arrives (lane k -> peer k)
        #pragma unroll
        for (int k = 0; k < 11; k++)
            if (lane == k) laneDelta = pdelta[k];
    }
    const uint32_t mbar_base = smem_u32(&sm.mbar[w][0]);

    float hnew = 0.0f;

    for (int t = 0; t < T; t++) {
        const int buf = t & 1;
        const int nxt = buf ^ 1;
        const float4* z4o = reinterpret_cast<const float4*>(&sm.zsD[buf][w][r][0]);
        const float4* h4  = reinterpret_cast<const float4*>(&sm.hg[w][0]);

        // ================= A: precompute from OWN state ========================
        float gh0a = sm.bhhS[lane],      gh0b = 0.f;
        float gh1a = sm.bhhS[32 + lane], gh1b = 0.f;
        float gh2a = sm.bhhS[64 + lane], gh2b = 0.f;
        {
            const float4* w0 = reinterpret_cast<const float4*>(&sm.whh2[(lane     )*36]);
            const float4* w1 = reinterpret_cast<const float4*>(&sm.whh2[(lane + 32)*36]);
            const float4* w2 = reinterpret_cast<const float4*>(&sm.whh2[(lane + 64)*36]);
            #pragma unroll
            for (int q = 0; q < 8; q++) {
                float4 a = h4[q];
                float4 x0 = w0[q], x1 = w1[q], x2 = w2[q];
                gh0a = fmaf(x0.x, a.x, gh0a); gh0b = fmaf(x0.y, a.y, gh0b);
                gh0a = fmaf(x0.z, a.z, gh0a); gh0b = fmaf(x0.w, a.w, gh0b);
                gh1a = fmaf(x1.x, a.x, gh1a); gh1b = fmaf(x1.y, a.y, gh1b);
                gh1a = fmaf(x1.z, a.z, gh1a); gh1b = fmaf(x1.w, a.w, gh1b);
                gh2a = fmaf(x2.x, a.x, gh2a); gh2b = fmaf(x2.y, a.y, gh2b);
                gh2a = fmaf(x2.z, a.z, gh2a); gh2b = fmaf(x2.w, a.w, gh2b);
            }
        }
        const float gh_r = gh0a + gh0b, gh_z = gh1a + gh1b, gh_n = gh2a + gh2b;

        float gvsa = sm.gsb[lane], gvsb = 0.f;
        {
            const float4* wg = reinterpret_cast<const float4*>(&sm.gsw2[lane*36]);
            #pragma unroll
            for (int q = 0; q < 8; q++) {
                float4 a = z4o[q], x = wg[q];
                gvsa = fmaf(x.x, a.x, gvsa); gvsb = fmaf(x.y, a.y, gvsb);
                gvsa = fmaf(x.z, a.z, gvsa); gvsb = fmaf(x.w, a.w, gvsb);
            }
        }

        float p0a = sm.lbS[lane],      p0b = 0.f;
        float p1a = sm.lbS[lane + 32], p1b = 0.f;
        {
            const float4* w0 = reinterpret_cast<const float4*>(&sm.lw2[(lane     )*68]);
            const float4* w1 = reinterpret_cast<const float4*>(&sm.lw2[(lane + 32)*68]);
            #pragma unroll
            for (int q = 0; q < 8; q++) {
                float4 a = z4o[q];
                float4 x0 = w0[q], x1 = w1[q];
                p0a = fmaf(x0.x, a.x, p0a); p0b = fmaf(x0.y, a.y, p0b);
                p0a = fmaf(x0.z, a.z, p0a); p0b = fmaf(x0.w, a.w, p0b);
                p1a = fmaf(x1.x, a.x, p1a); p1b = fmaf(x1.y, a.y, p1b);
                p1a = fmaf(x1.z, a.z, p1a); p1b = fmaf(x1.w, a.w, p1b);
            }
        }

        // ================= B: wait for peers' z(t-1) (local mbarrier) ==========
        if (t > 0)
            mbar_wait(mbar_base + (uint32_t)(((t - 1) & 1) * 8),
                      (uint32_t)(((t - 1) >> 1) & 1));

        // ================= C: messages + projection -> inc =====================
        float inc0 = 0.f, inc1 = 0.f, inc2 = 0.f, inc3 = 0.f;
        float mvreg[6];
        #pragma unroll
        for (int rd = 0; rd < 6; rd++) {
            const int ep = 2*rd;
            const int eslot = ep + sub;
            if (eslot < 11) {
                const int s = sm.slist[eslot];
                const float4* w4 = reinterpret_cast<const float4*>(&sm.mw2[(eslot*16 + m16)*36]);
                const float4* a4 = reinterpret_cast<const float4*>(&sm.zsD[buf][w][s][0]);
                float acc0 = sm.mb[eslot*16 + m16], acc1 = 0.f;
                #pragma unroll
                for (int q = 0; q < 8; q++) {
                    float4 x = w4[q], a = a4[q];
                    acc0 = fmaf(x.x, a.x, acc0); acc1 = fmaf(x.y, a.y, acc1);
                    acc0 = fmaf(x.z, a.z, acc0); acc1 = fmaf(x.w, a.w, acc1);
                }
                const float mv = acc0 + acc1;
                sm.meanS[w][sub][m16] = mv;
                mvreg[rd] = mv;
            }
            __syncwarp();
            const int n2 = (ep + 1 < 11) ? 2 : 1;
            for (int ss = 0; ss < n2; ss++) {
                const float4* w4 = reinterpret_cast<const float4*>(&sm.aw2[((ep + ss)*32 + lane)*20]);
                const float4* a4 = reinterpret_cast<const float4*>(&sm.meanS[w][ss][0]);
                #pragma unroll
                for (int q = 0; q < 4; q++) {
                    float4 x = w4[q], a = a4[q];
                    inc0 = fmaf(x.x, a.x, inc0); inc1 = fmaf(x.y, a.y, inc1);
                    inc2 = fmaf(x.z, a.z, inc2); inc3 = fmaf(x.w, a.w, inc3);
                }
            }
            __syncwarp();
        }
        const float incv = (inc0 + inc1) + (inc2 + inc3);
        sm.incS[w][lane] = incv;
        __syncwarp();
        const float4* inc4 = reinterpret_cast<const float4*>(&sm.incS[w][0]);

        // ================= D: gate =============================================
        {
            const float4* wg = reinterpret_cast<const float4*>(&sm.gcw2[lane*36]);
            #pragma unroll
            for (int q = 0; q < 8; q++) {
                float4 a = inc4[q], x = wg[q];
                gvsa = fmaf(x.x, a.x, gvsa); gvsb = fmaf(x.y, a.y, gvsb);
                gvsa = fmaf(x.z, a.z, gvsa); gvsb = fmaf(x.w, a.w, gvsb);
            }
        }
        const float gate = fsig(gvsa + gvsb);

        // ================= E: hidden inc-half, silu, out, z update =============
        {
            const float4* w0 = reinterpret_cast<const float4*>(&sm.lw2[(lane     )*68 + 32]);
            const float4* w1 = reinterpret_cast<const float4*>(&sm.lw2[(lane + 32)*68 + 32]);
            #pragma unroll
            for (int q = 0; q < 8; q++) {
                float4 a = inc4[q];
                float4 x0 = w0[q], x1 = w1[q];
                p0a = fmaf(x0.x, a.x, p0a); p0b = fmaf(x0.y, a.y, p0b);
                p0a = fmaf(x0.z, a.z, p0a); p0b = fmaf(x0.w, a.w, p0b);
                p1a = fmaf(x1.x, a.x, p1a); p1b = fmaf(x1.y, a.y, p1b);
                p1a = fmaf(x1.z, a.z, p1a); p1b = fmaf(x1.w, a.w, p1b);
            }
        }
        const float pv0 = p0a + p0b, pv1 = p1a + p1b;
        sm.hbuf[w][lane]      = pv0 * fsig(pv0);
        sm.hbuf[w][lane + 32] = pv1 * fsig(pv1);
        __syncwarp();

        float tva = sm.obS[lane], tvb = 0.f, tvc = 0.f, tvd = 0.f;
        {
            const float4* w4 = reinterpret_cast<const float4*>(&sm.ow2[lane*68]);
            const float4* a4 = reinterpret_cast<const float4*>(&sm.hbuf[w][0]);
            #pragma unroll
            for (int q = 0; q < 16; q++) {
                float4 a = a4[q], x = w4[q];
                tva = fmaf(x.x, a.x, tva); tvb = fmaf(x.y, a.y, tvb);
                tvc = fmaf(x.z, a.z, tvc); tvd = fmaf(x.w, a.w, tvd);
            }
        }
        const float target = tanhf((tva + tvb) + (tvc + tvd));
        const float zold = sm.zsD[buf][w][r][lane];
        const float znew = fmaf(0.1f * gate, target - zold, zold);

        // ================= publish z via DSMEM (critical path) =================
        sm.zsD[nxt][w][r][lane] = znew;     // local copy for own next step
        __syncwarp();
        {
            const uint32_t zaddr = smem_base +
                (uint32_t)((char*)&sm.zsD[nxt][w][r][lane] - (char*)&sm);
            #pragma unroll
            for (int k = 0; k < 11; k++)
                st_remote_f32(zaddr + pdelta[k], znew);
            __syncwarp();
            if (lane < 11)
                mbar_arrive_remote(mbar_base + (uint32_t)((t & 1) * 8) + laneDelta);
        }

        // ================= off-critical-path: outputs + GRU ====================
        zt[(((size_t)b*T + t)*RB + r)*LB + lane] = znew;
        {
            float* msbase = ms + ((size_t)b*T + t)*(EB*MB);
            #pragma unroll
            for (int rd = 0; rd < 6; rd++) {
                const int slot = 2*rd + sub;
                if (slot < 11)
                    msbase[(size_t)sm.elist[slot]*MB + m16] = mvreg[rd];
            }
        }
        float gi0a = sm.bihS[lane],      gi0b = 0.f;
        float gi1a = sm.bihS[32 + lane], gi1b = 0.f;
        float gi2a = sm.bihS[64 + lane], gi2b = 0.f;
        {
            const float4* w0 = reinterpret_cast<const float4*>(&sm.wih2[(lane     )*36]);
            const float4* w1 = reinterpret_cast<const float4*>(&sm.wih2[(lane + 32)*36]);
            const float4* w2 = reinterpret_cast<const float4*>(&sm.wih2[(lane + 64)*36]);
            #pragma unroll
            for (int q = 0; q < 8; q++) {
                float4 a = inc4[q];
                float4 x0 = w0[q], x1 = w1[q], x2 = w2[q];
                gi0a = fmaf(x0.x, a.x, gi0a); gi0b = fmaf(x0.y, a.y, gi0b);
                gi0a = fmaf(x0.z, a.z, gi0a); gi0b = fmaf(x0.w, a.w, gi0b);
                gi1a = fmaf(x1.x, a.x, gi1a); gi1b = fmaf(x1.y, a.y, gi1b);
                gi1a = fmaf(x1.z, a.z, gi1a); gi1b = fmaf(x1.w, a.w, gi1b);
                gi2a = fmaf(x2.x, a.x, gi2a); gi2b = fmaf(x2.y, a.y, gi2b);
                gi2a = fmaf(x2.z, a.z, gi2a); gi2b = fmaf(x2.w, a.w, gi2b);
            }
        }
        const float reset = fsig((gi0a + gi0b) + gh_r);
        const float upd   = fsig((gi1a + gi1b) + gh_z);
        const float nn    = tanhf(fmaf(reset, gh_n, gi2a + gi2b));
        const float hold  = sm.hg[w][lane];
        hnew = (1.0f - upd) * nn + upd * hold;
        sm.hg[w][lane] = hnew;
        __syncwarp();
    }

    hf[((size_t)b*RB + r)*HHB + lane] = hnew;

    __syncthreads();
    cluster_sync_all();   // no CTA exits while peers may still write its smem
}

extern "C" void kernel_launch(void* const* d_in, const int* in_sizes, int n_in,
                              void* d_out, int out_size) {
    const float* z0     = (const float*)d_in[0];
    const float* h0     = (const float*)d_in[1];
    const float* mean_w = (const float*)d_in[2];
    const float* mean_b = (const float*)d_in[3];
    const float* add_w  = (const float*)d_in[4];
    const float* gsw    = (const float*)d_in[5];
    const float* gsb    = (const float*)d_in[6];
    const float* gcw    = (const float*)d_in[7];
    const float* lw     = (const float*)d_in[8];
    const float* lb     = (const float*)d_in[9];
    const float* ow     = (const float*)d_in[10];
    const float* ob     = (const float*)d_in[11];
    const float* wih    = (const float*)d_in[12];
    const float* whh    = (const float*)d_in[13];
    const float* bih    = (const float*)d_in[14];
    const float* bhh    = (const float*)d_in[15];
    const int* src_idx  = (const int*)d_in[16];
    const int* tgt_idx  = (const int*)d_in[17];
    // out_size = B*T*R*L + B*R*Hh + B*T*E*M
    const int per_t = BTOT*RB*LB + BTOT*EB*MB;
    const int T = (out_size - BTOT*RB*HHB) / per_t;

    float* out = (float*)d_out;
    float* zt = out;
    float* hf = zt + (size_t)BTOT * T * RB * LB;
    float* ms = hf + (size_t)BTOT * RB * HHB;

    cudaFuncSetAttribute(nv_main_kernel,
                         cudaFuncAttributeMaxDynamicSharedMemorySize,
                         (int)sizeof(SmemLayout));
    cudaFuncSetAttribute(nv_main_kernel,
                         cudaFuncAttributeNonPortableClusterSizeAllowed, 1);

    nv_main_kernel<<<NBLOCKS, NTHREADS, sizeof(SmemLayout)>>>(
        z0, h0, mean_w, mean_b, add_w, gsw, gsb, gcw, lw, lb, ow, ob,
        wih, whh, bih, bhh, src_idx, tgt_idx, T, zt, hf, ms);
}